// round 8
// baseline (speedup 1.0000x reference)
#include <cuda_runtime.h>
#include <cuda_fp16.h>
#include <cstdint>

#define GRID  128
#define NTHR  512
#define NWARP 16
#define TOTWARP 2048
#define BSZ   128
#define TE    512
#define HD    256
#define MELD  80
#define RF    5
#define STEPS 200
#define G3    768
#define SMEM_BYTES 33280   // 32 * 65 * 16 (prelude X staging, K=256 padded)

// ---------------- device scratch ----------------------------------------------------
__device__ __half g_w1h[(size_t)BSZ * TE * HD];   // w1enc in fp16 (33.5 MB)
__device__ __half g_ench[(size_t)BSZ * TE * HD];  // enc in fp16 (33.5 MB)
__device__ float g_pre1[STEPS * BSZ * HD];
__device__ float g_xs[STEPS * BSZ * (HD / 2)];
__device__ float g_giatt[(size_t)STEPS * BSZ * G3];
__device__ float g_dbuf[2][BSZ * HD];
__device__ float g_h1buf[2][BSZ * HD];
__device__ float g_h2buf[2][BSZ * HD];
__device__ float g_q[BSZ * HD];
__device__ float g_ddot[BSZ * HD];
__device__ float g_p[BSZ * HD];
__device__ float g_in2[BSZ * HD];
__device__ float g_s[BSZ * HD];
__device__ unsigned g_bar_count;
__device__ unsigned g_bar_epoch;

// ---------------- helpers -----------------------------------------------------------
__device__ __forceinline__ float tanh_fast(float x) {
    float y; asm("tanh.approx.f32 %0, %1;" : "=f"(y) : "f"(x)); return y;
}
__device__ __forceinline__ float sigmoidf_(float x) { return 1.f / (1.f + __expf(-x)); }
__device__ __forceinline__ unsigned ld_acq(const unsigned* p) {
    unsigned v; asm volatile("ld.acquire.gpu.b32 %0, [%1];" : "=r"(v) : "l"(p)); return v;
}

__device__ __forceinline__ void gsync(unsigned target)
{
    __syncthreads();
    if (threadIdx.x == 0) {
        __threadfence();
        unsigned a = atomicAdd(&g_bar_count, 1u);
        if (a == GRID - 1u) {
            g_bar_count = 0u;
            __threadfence();
            atomicAdd(&g_bar_epoch, 1u);
        } else {
            while ((int)(ld_acq(&g_bar_epoch) - target) < 0) { }
        }
    }
    __syncthreads();
}

// 64-MAC dot of one K-quarter (16 float4)
__device__ __forceinline__ float dot64(const float4* __restrict__ w,
                                       const float4* __restrict__ x)
{
    float acc = 0.f;
#pragma unroll
    for (int i = 0; i < 16; i++) {
        float4 a = w[i], b = x[i];
        acc = fmaf(a.x, b.x, acc); acc = fmaf(a.y, b.y, acc);
        acc = fmaf(a.z, b.z, acc); acc = fmaf(a.w, b.w, acc);
    }
    return acc;
}
// three gate rows (stride 16384 float4 = 256*256 floats) sharing one x stream
__device__ __forceinline__ void dot64x3(const float4* __restrict__ w,
                                        const float4* __restrict__ x,
                                        float& a0, float& a1, float& a2)
{
#pragma unroll
    for (int i = 0; i < 16; i++) {
        float4 b = x[i];
        float4 p = w[i];
        a0 = fmaf(p.x, b.x, a0); a0 = fmaf(p.y, b.y, a0);
        a0 = fmaf(p.z, b.z, a0); a0 = fmaf(p.w, b.w, a0);
        float4 q = w[i + 16384];
        a1 = fmaf(q.x, b.x, a1); a1 = fmaf(q.y, b.y, a1);
        a1 = fmaf(q.z, b.z, a1); a1 = fmaf(q.w, b.w, a1);
        float4 r = w[i + 32768];
        a2 = fmaf(r.x, b.x, a2); a2 = fmaf(r.y, b.y, a2);
        a2 = fmaf(r.z, b.z, a2); a2 = fmaf(r.w, b.w, a2);
    }
}
__device__ __forceinline__ float qred(float a) {
    a += __shfl_xor_sync(0xffffffffu, a, 1);
    a += __shfl_xor_sync(0xffffffffu, a, 2);
    return a;
}

// ---------------- per-step GEMV: Y[b,j] = X[b,:]@W[j,:] + bias, K=256 ---------------
// warp unit: 8 cols (quad each), lanes split K in 4 chunks of 64.
__device__ void dev_gemv(const float* __restrict__ X, const float* __restrict__ W,
                         const float* __restrict__ bias, float* __restrict__ Y,
                         long ldy, int jgs)
{
    const int lane = threadIdx.x & 31, quad = lane >> 2, ks = lane & 3;
    const int wg = blockIdx.x * NWARP + (threadIdx.x >> 5);
    const int units = BSZ * jgs;
    for (int u = wg; u < units; u += TOTWARP) {
        const int b = u / jgs, jg = u - b * jgs;
        const int j = jg * 8 + quad;
        const float4* W4 = (const float4*)W + (size_t)j * 64 + ks * 16;
        const float4* X4 = (const float4*)(X + (size_t)b * HD) + ks * 16;
        float acc = qred(dot64(W4, X4));
        if (ks == 0) Y[(long)b * ldy + j] = acc + bias[j];
    }
}

// ---------------- proj: K=512 concat [d | ddot] -> p --------------------------------
__device__ void dev_proj(const float* __restrict__ D, const float* __restrict__ Dd,
                         const float* __restrict__ W, const float* __restrict__ bias,
                         float* __restrict__ Y)
{
    const int lane = threadIdx.x & 31, quad = lane >> 2, ks = lane & 3;
    const int wg = blockIdx.x * NWARP + (threadIdx.x >> 5);
    for (int u = wg; u < BSZ * 32; u += TOTWARP) {
        const int b = u >> 5, jg = u & 31;
        const int j = jg * 8 + quad;
        const float4* W4 = (const float4*)W + (size_t)j * 128 + ks * 32;
        const float* xs = (ks < 2) ? (D + (size_t)b * HD + ks * 128)
                                   : (Dd + (size_t)b * HD + (ks - 2) * 128);
        const float4* X4 = (const float4*)xs;
        float acc = 0.f;
#pragma unroll
        for (int i = 0; i < 32; i++) {
            float4 a = W4[i], x = X4[i];
            acc = fmaf(a.x, x.x, acc); acc = fmaf(a.y, x.y, acc);
            acc = fmaf(a.z, x.z, acc); acc = fmaf(a.w, x.w, acc);
        }
        acc = qred(acc);
        if (ks == 0) Y[(size_t)b * HD + j] = acc + bias[j];
    }
}

// ---------------- GRU step ----------------------------------------------------------
__device__ void dev_gru(const float* __restrict__ GIpre, const float* __restrict__ X,
                        const float* __restrict__ Wih, const float* __restrict__ bih,
                        const float* __restrict__ Whh, const float* __restrict__ bhh,
                        const float* __restrict__ H, float* __restrict__ Hnew,
                        float* __restrict__ Sum)
{
    const int lane = threadIdx.x & 31, quad = lane >> 2, ks = lane & 3;
    const int wg = blockIdx.x * NWARP + (threadIdx.x >> 5);
    for (int u = wg; u < BSZ * 32; u += TOTWARP) {
        const int b = u >> 5, jg = u & 31;
        const int j = jg * 8 + quad;
        const float4* H4 = (const float4*)(H + (size_t)b * HD) + ks * 16;
        const float4* V4 = (const float4*)Whh + (size_t)j * 64 + ks * 16;
        float hr = 0.f, hz = 0.f, hn = 0.f;
        dot64x3(V4, H4, hr, hz, hn);
        float ir = 0.f, iz = 0.f, in_ = 0.f;
        if (X) {
            const float4* X4 = (const float4*)(X + (size_t)b * HD) + ks * 16;
            const float4* U4 = (const float4*)Wih + (size_t)j * 64 + ks * 16;
            dot64x3(U4, X4, ir, iz, in_);
        }
        hr = qred(hr); hz = qred(hz); hn = qred(hn);
        ir = qred(ir); iz = qred(iz); in_ = qred(in_);
        if (ks == 0) {
            if (GIpre) {
                const float* gp = GIpre + (size_t)b * G3 + j;
                ir = gp[0]; iz = gp[HD]; in_ = gp[2 * HD];
            } else {
                ir += bih[j]; iz += bih[j + HD]; in_ += bih[j + 2 * HD];
            }
            float rg = sigmoidf_(ir + hr + bhh[j]);
            float zg = sigmoidf_(iz + hz + bhh[j + HD]);
            float ng = tanhf(in_ + rg * (hn + bhh[j + 2 * HD]));
            float hv = H[(size_t)b * HD + j];
            float val = (1.f - zg) * ng + zg * hv;
            Hnew[(size_t)b * HD + j] = val;
            if (Sum) Sum[(size_t)b * HD + j] = val + X[(size_t)b * HD + j];
        }
    }
}

// ---------------- fused attention: scores -> softmax -> context (block = batch b) ---
__device__ void dev_attn(const float* __restrict__ vw, const float* __restrict__ vb,
                         float* smf)
{
    float* sexp = smf;            // 512
    float* red  = smf + 512;      // 16
    float* pacc = smf + 544;      // 4*256
    const int tid = threadIdx.x, lane = tid & 31, wid = tid >> 5;
    const int b = blockIdx.x;
    const float vb0 = vb[0];

    // preload q and v for this lane's 8 h positions
    float2 q2[4], v2[4];
#pragma unroll
    for (int m = 0; m < 4; m++) {
        q2[m] = *((const float2*)(g_q + (size_t)b * HD) + lane + m * 32);
        v2[m] = *((const float2*)vw + lane + m * 32);
    }
    // scores: warp handles 32 t rows
    const __half2* wb = (const __half2*)g_w1h + (size_t)b * TE * (HD / 2);
#pragma unroll 2
    for (int i = 0; i < 32; i++) {
        const int t = wid * 32 + i;
        const __half2* r2 = wb + (size_t)t * (HD / 2) + lane;
        float acc = 0.f;
#pragma unroll
        for (int m = 0; m < 4; m++) {
            float2 w = __half22float2(r2[m * 32]);
            acc += v2[m].x * tanh_fast(w.x + q2[m].x)
                 + v2[m].y * tanh_fast(w.y + q2[m].y);
        }
        for (int o = 16; o; o >>= 1) acc += __shfl_down_sync(0xffffffffu, acc, o);
        if (lane == 0) sexp[t] = acc + vb0;
    }
    __syncthreads();

    // softmax over 512 (one score per thread)
    float s = sexp[tid];
    float m_ = s;
    for (int o = 16; o; o >>= 1) m_ = fmaxf(m_, __shfl_xor_sync(0xffffffffu, m_, o));
    if (lane == 0) red[wid] = m_;
    __syncthreads();
    float mx = red[0];
#pragma unroll
    for (int k = 1; k < NWARP; k++) mx = fmaxf(mx, red[k]);
    float e = __expf(s - mx);
    float ss = e;
    for (int o = 16; o; o >>= 1) ss += __shfl_xor_sync(0xffffffffu, ss, o);
    __syncthreads();                 // all reads of red/sexp done
    sexp[tid] = e;
    if (lane == 0) red[wid] = ss;
    __syncthreads();
    float sum = red[0];
#pragma unroll
    for (int k = 1; k < NWARP; k++) sum += red[k];
    const float inv = 1.f / sum;

    // context: thread = (h2 = tid&127, tq = tid>>7); each covers 128 t
    const int h2 = tid & 127, tq = tid >> 7;
    const __half2* e2 = (const __half2*)g_ench
                      + ((size_t)b * TE + tq * 128) * (HD / 2) + h2;
    float ax = 0.f, ay = 0.f;
#pragma unroll 8
    for (int tt = 0; tt < 128; tt++) {
        float2 v = __half22float2(e2[(size_t)tt * (HD / 2)]);
        float uu = sexp[tq * 128 + tt];
        ax = fmaf(uu, v.x, ax); ay = fmaf(uu, v.y, ay);
    }
    pacc[tq * 256 + h2 * 2]     = ax;
    pacc[tq * 256 + h2 * 2 + 1] = ay;
    __syncthreads();
    if (tid < HD) {
        float r = pacc[tid] + pacc[256 + tid] + pacc[512 + tid] + pacc[768 + tid];
        g_ddot[(size_t)b * HD + tid] = r * inv;
    }
}

// ---------------- prelude tiled GEMM (32 rows x 64 cols per tile) -------------------
__device__ void dev_linear(const float* __restrict__ X, const float* __restrict__ dec,
                           int nf4, const float* __restrict__ W,
                           const float* __restrict__ bias,
                           float* __restrict__ Yf, __half* __restrict__ Yh,
                           int ldy, int relu, int nrt, int ncp, float4* sm4)
{
    const int tid = threadIdx.x, lane = tid & 31, wid = tid >> 5;
    const int stride4 = nf4 + 1;
    const int tiles = nrt * ncp;
    for (int t = blockIdx.x; t < tiles; t += GRID) {
        const int rt = t / ncp, cp = t - rt * ncp;
        const long r0 = (long)rt * 32;
        for (int idx = tid; idx < 32 * nf4; idx += NTHR) {
            int row = idx / nf4, c4 = idx - row * nf4;
            long r = r0 + row;
            float4 v;
            if (dec) v = *(const float4*)(dec + (r & 127) * 80000L
                                          + (r >> 7) * (RF * MELD) + c4 * 4);
            else     v = *(const float4*)(X + r * (long)(nf4 * 4) + c4 * 4);
            sm4[row * stride4 + c4] = v;
        }
        __syncthreads();
        const int j0 = cp * 64 + wid * 4;
        const float4* W4 = (const float4*)W + (size_t)j0 * nf4;
        const float4* xr = sm4 + lane * stride4;
        float a0 = bias[j0], a1 = bias[j0 + 1], a2 = bias[j0 + 2], a3 = bias[j0 + 3];
#pragma unroll 4
        for (int k = 0; k < nf4; k++) {
            float4 x = xr[k];
            float4 w0 = W4[k];
            a0 = fmaf(w0.x, x.x, a0); a0 = fmaf(w0.y, x.y, a0);
            a0 = fmaf(w0.z, x.z, a0); a0 = fmaf(w0.w, x.w, a0);
            float4 w1 = W4[nf4 + k];
            a1 = fmaf(w1.x, x.x, a1); a1 = fmaf(w1.y, x.y, a1);
            a1 = fmaf(w1.z, x.z, a1); a1 = fmaf(w1.w, x.w, a1);
            float4 w2 = W4[2 * nf4 + k];
            a2 = fmaf(w2.x, x.x, a2); a2 = fmaf(w2.y, x.y, a2);
            a2 = fmaf(w2.z, x.z, a2); a2 = fmaf(w2.w, x.w, a2);
            float4 w3 = W4[3 * nf4 + k];
            a3 = fmaf(w3.x, x.x, a3); a3 = fmaf(w3.y, x.y, a3);
            a3 = fmaf(w3.z, x.z, a3); a3 = fmaf(w3.w, x.w, a3);
        }
        if (relu) {
            a0 = fmaxf(a0, 0.f); a1 = fmaxf(a1, 0.f);
            a2 = fmaxf(a2, 0.f); a3 = fmaxf(a3, 0.f);
        }
        const long orow = (r0 + lane) * (long)ldy + j0;
        if (Yh) {
            Yh[orow] = __float2half(a0);     Yh[orow + 1] = __float2half(a1);
            Yh[orow + 2] = __float2half(a2); Yh[orow + 3] = __float2half(a3);
        } else {
            Yf[orow] = a0; Yf[orow + 1] = a1; Yf[orow + 2] = a2; Yf[orow + 3] = a3;
        }
        __syncthreads();
    }
}

// ---------------- persistent kernel -------------------------------------------------
__global__ void __launch_bounds__(NTHR, 1)
mel_persist(const float* __restrict__ enc, const float* __restrict__ dec,
            const float* pre_w1, const float* pre_b1,
            const float* pre_w2, const float* pre_b2,
            const float* w1, const float* b1, const float* w2, const float* b2,
            const float* v_w, const float* v_b,
            const float* proj_w, const float* proj_b,
            const float* out_w, const float* out_b,
            const float* att_wih, const float* att_whh,
            const float* att_bih, const float* att_bhh,
            const float* g1_wih, const float* g1_whh,
            const float* g1_bih, const float* g1_bhh,
            const float* g2_wih, const float* g2_whh,
            const float* g2_bih, const float* g2_bhh,
            float* __restrict__ out)
{
    extern __shared__ float4 sm4[];
    float* smf = (float*)sm4;
    const unsigned base = ld_acq(&g_bar_epoch);
    unsigned ep = 0;
#define GS() gsync(base + (++ep))

    // P0: zero states + fp16 copy of enc
    {
        const int gtid = blockIdx.x * NTHR + threadIdx.x;
        for (int i = gtid; i < BSZ * HD; i += GRID * NTHR) {
            g_dbuf[0][i] = 0.f;  g_dbuf[1][i] = 0.f;
            g_h1buf[0][i] = 0.f; g_h1buf[1][i] = 0.f;
            g_h2buf[0][i] = 0.f; g_h2buf[1][i] = 0.f;
        }
        const float4* e4 = (const float4*)enc;
        __half2* o2 = (__half2*)g_ench;
        const int n4 = (BSZ * TE * HD) / 4;
        for (int i = gtid; i < n4; i += GRID * NTHR) {
            float4 v = e4[i];
            o2[2 * i]     = __floats2half2_rn(v.x, v.y);
            o2[2 * i + 1] = __floats2half2_rn(v.z, v.w);
        }
    }
    // P1: pre-net L1 (dec gather): [25600,80] -> [25600,256] relu
    dev_linear(nullptr, dec, 20, pre_w1, pre_b1, g_pre1, nullptr, HD, 1, 800, 4, sm4);
    GS();
    // P2: pre-net L2 -> [25600,128] relu
    dev_linear(g_pre1, nullptr, 64, pre_w2, pre_b2, g_xs, nullptr, 128, 1, 800, 2, sm4);
    GS();
    // P3: att GRU input gates all steps -> [25600,768]
    dev_linear(g_xs, nullptr, 32, att_wih, att_bih, g_giatt, nullptr, G3, 0, 800, 12, sm4);
    GS();
    // P4: w1enc (fp16) = enc @ w1^T + b1 : [65536,256]
    dev_linear(enc, nullptr, 64, w1, b1, nullptr, g_w1h, HD, 0, 2048, 4, sm4);
    GS();

    for (int i = 0; i < STEPS; i++) {
        const int cur = i & 1, prev = cur ^ 1;
        float* dprev = g_dbuf[prev]; float* dcur = g_dbuf[cur];

        // A: attention GRU (input gates precomputed)
        dev_gru(g_giatt + (size_t)i * BSZ * G3, nullptr, nullptr, nullptr,
                att_whh, att_bhh, dprev, dcur, nullptr);
        GS();
        // B: q = d @ w2^T + b2
        dev_gemv(dcur, w2, b2, g_q, HD, 32);
        GS();
        // C: scores + softmax + context (fused, block = b)
        dev_attn(v_w, v_b, smf);
        GS();
        // D: p = [d | ddot] @ proj_w^T + proj_b
        dev_proj(dcur, g_ddot, proj_w, proj_b, g_p);
        GS();
        // E: GRU1; in2 = p + o1
        dev_gru(nullptr, g_p, g1_wih, g1_bih, g1_whh, g1_bhh,
                g_h1buf[prev], g_h1buf[cur], g_in2);
        GS();
        // F: GRU2; s = in2 + o2
        dev_gru(nullptr, g_in2, g2_wih, g2_bih, g2_whh, g2_bhh,
                g_h2buf[prev], g_h2buf[cur], g_s);
        GS();
        // G: out = s @ out_w^T + out_b, scattered rows (no trailing barrier:
        // next A touches only dbuf, disjoint; covered by A's barrier)
        dev_gemv(g_s, out_w, out_b, out + (size_t)i * RF * MELD, 1000L * MELD, 50);
    }
#undef GS
}

// ---------------- host launch -------------------------------------------------------
extern "C" void kernel_launch(void* const* d_in, const int* in_sizes, int n_in,
                              void* d_out, int out_size)
{
    cudaFuncSetAttribute(mel_persist, cudaFuncAttributeMaxDynamicSharedMemorySize,
                         SMEM_BYTES);
    mel_persist<<<GRID, NTHR, SMEM_BYTES>>>(
        (const float*)d_in[0],  (const float*)d_in[1],
        (const float*)d_in[2],  (const float*)d_in[3],
        (const float*)d_in[4],  (const float*)d_in[5],
        (const float*)d_in[6],  (const float*)d_in[7],
        (const float*)d_in[8],  (const float*)d_in[9],
        (const float*)d_in[10], (const float*)d_in[11],
        (const float*)d_in[12], (const float*)d_in[13],
        (const float*)d_in[14], (const float*)d_in[15],
        (const float*)d_in[16], (const float*)d_in[17],
        (const float*)d_in[18], (const float*)d_in[19],
        (const float*)d_in[20], (const float*)d_in[21],
        (const float*)d_in[22], (const float*)d_in[23],
        (const float*)d_in[24], (const float*)d_in[25],
        (const float*)d_in[26], (const float*)d_in[27],
        (float*)d_out);
}

// round 10
// speedup vs baseline: 2.7137x; 2.7137x over previous
#include <cuda_runtime.h>
#include <cuda_fp16.h>
#include <cstdint>

#define GRID  128
#define NTHR  512
#define BSZ   128
#define TE    512
#define HD    256
#define MELD  80
#define RF    5
#define STEPS 200
#define G3    768
// smem: xs[256*33] + hs[256*33] floats, + attn region 2064 floats
#define XS_F   (256 * 33)
#define ATTN_F (2 * XS_F)
#define SMEM_BYTES ((ATTN_F + 2064) * 4)   // 75,840 B

// ---------------- device scratch (transposed [dim][BSZ] for step vectors) -----------
__device__ __half g_w1h[(size_t)BSZ * TE * HD];   // [b][t][h] fp16
__device__ __half g_ench[(size_t)BSZ * TE * HD];  // [b][t][h] fp16
__device__ float g_pre1[STEPS * BSZ * HD];
__device__ float g_xs[STEPS * BSZ * (HD / 2)];
__device__ float g_giatt[(size_t)STEPS * G3 * BSZ];  // [step][j][b]  (transposed!)
__device__ float g_dbuf[2][HD * BSZ];
__device__ float g_h1buf[2][HD * BSZ];
__device__ float g_h2buf[2][HD * BSZ];
__device__ float g_q[HD * BSZ];
__device__ float g_ddot[HD * BSZ];
__device__ float g_p[HD * BSZ];
__device__ float g_in2[HD * BSZ];
__device__ float g_s[HD * BSZ];
__device__ unsigned g_bar_count;
__device__ unsigned g_bar_epoch;

// ---------------- helpers -----------------------------------------------------------
__device__ __forceinline__ float tanh_fast(float x) {
    float y; asm("tanh.approx.f32 %0, %1;" : "=f"(y) : "f"(x)); return y;
}
__device__ __forceinline__ float sigmoidf_(float x) { return 1.f / (1.f + __expf(-x)); }
__device__ __forceinline__ unsigned ld_acq(const unsigned* p) {
    unsigned v; asm volatile("ld.acquire.gpu.b32 %0, [%1];" : "=r"(v) : "l"(p)); return v;
}

__device__ __forceinline__ void gsync(unsigned target)
{
    __syncthreads();
    if (threadIdx.x == 0) {
        __threadfence();
        unsigned a = atomicAdd(&g_bar_count, 1u);
        if (a == GRID - 1u) {
            g_bar_count = 0u;
            __threadfence();
            atomicAdd(&g_bar_epoch, 1u);
        } else {
            while ((int)(ld_acq(&g_bar_epoch) - target) < 0) { }
        }
    }
    __syncthreads();
}

// ---------------- staging: src_t [K][128] -> smem xs[k*33 + bl] for 32 b-cols --------
__device__ __forceinline__ void stage_t(const float* __restrict__ src, int K,
                                        float* __restrict__ xs)
{
    const int b0 = (blockIdx.x & 3) << 5;
    for (int idx = threadIdx.x; idx < 32 * K; idx += NTHR) {
        const int k = idx >> 5, bl = idx & 31;
        xs[k * 33 + bl] = src[k * BSZ + b0 + bl];   // coalesced LDG, conflict-free STS
    }
}

// ---------------- GRU step: warp = one j (weights uniform), lanes = 32 b ------------
// 8 active warps; j = (bid>>2) + 32*w covers [0,256) once per btile.
__device__ void gru_t(const float* __restrict__ gi_t,   // [768][128] (incl. bih) or null
                      const float* __restrict__ Wih,    // [768][256] (if gi_t null)
                      const float* __restrict__ bih,
                      const float* __restrict__ Whh,    // [768][256]
                      const float* __restrict__ bhh,
                      const float* __restrict__ Hs,     // smem [256][33]
                      const float* __restrict__ Xs,     // smem [256][33] or null
                      float* __restrict__ Hnew_t,       // [256][128]
                      float* __restrict__ Sum_t)        // [256][128] or null
{
    const int w = threadIdx.x >> 5, lane = threadIdx.x & 31;
    if (w < 8) {
        const int j = (blockIdx.x >> 2) + (w << 5);
        const int b = ((blockIdx.x & 3) << 5) + lane;
        const float4* Wr4 = (const float4*)Whh + (size_t)j * 64;
        const float4* Wz4 = Wr4 + (size_t)HD * 64;
        const float4* Wn4 = Wz4 + (size_t)HD * 64;
        float hr = 0.f, hz = 0.f, hn = 0.f;
#pragma unroll 8
        for (int k4 = 0; k4 < 64; k4++) {
            const float4 a = Wr4[k4], c = Wz4[k4], d = Wn4[k4];
            const float h0 = Hs[(4 * k4 + 0) * 33 + lane];
            const float h1 = Hs[(4 * k4 + 1) * 33 + lane];
            const float h2 = Hs[(4 * k4 + 2) * 33 + lane];
            const float h3 = Hs[(4 * k4 + 3) * 33 + lane];
            hr = fmaf(a.x, h0, hr); hr = fmaf(a.y, h1, hr);
            hr = fmaf(a.z, h2, hr); hr = fmaf(a.w, h3, hr);
            hz = fmaf(c.x, h0, hz); hz = fmaf(c.y, h1, hz);
            hz = fmaf(c.z, h2, hz); hz = fmaf(c.w, h3, hz);
            hn = fmaf(d.x, h0, hn); hn = fmaf(d.y, h1, hn);
            hn = fmaf(d.z, h2, hn); hn = fmaf(d.w, h3, hn);
        }
        float ir, iz, inn;
        if (gi_t) {
            ir  = gi_t[(size_t)j * BSZ + b];
            iz  = gi_t[(size_t)(j + HD) * BSZ + b];
            inn = gi_t[(size_t)(j + 2 * HD) * BSZ + b];
        } else {
            const float4* Ur4 = (const float4*)Wih + (size_t)j * 64;
            const float4* Uz4 = Ur4 + (size_t)HD * 64;
            const float4* Un4 = Uz4 + (size_t)HD * 64;
            float r_ = 0.f, z_ = 0.f, n_ = 0.f;
#pragma unroll 8
            for (int k4 = 0; k4 < 64; k4++) {
                const float4 a = Ur4[k4], c = Uz4[k4], d = Un4[k4];
                const float x0 = Xs[(4 * k4 + 0) * 33 + lane];
                const float x1 = Xs[(4 * k4 + 1) * 33 + lane];
                const float x2 = Xs[(4 * k4 + 2) * 33 + lane];
                const float x3 = Xs[(4 * k4 + 3) * 33 + lane];
                r_ = fmaf(a.x, x0, r_); r_ = fmaf(a.y, x1, r_);
                r_ = fmaf(a.z, x2, r_); r_ = fmaf(a.w, x3, r_);
                z_ = fmaf(c.x, x0, z_); z_ = fmaf(c.y, x1, z_);
                z_ = fmaf(c.z, x2, z_); z_ = fmaf(c.w, x3, z_);
                n_ = fmaf(d.x, x0, n_); n_ = fmaf(d.y, x1, n_);
                n_ = fmaf(d.z, x2, n_); n_ = fmaf(d.w, x3, n_);
            }
            ir = r_ + bih[j]; iz = z_ + bih[j + HD]; inn = n_ + bih[j + 2 * HD];
        }
        const float rg = sigmoidf_(ir + hr + bhh[j]);
        const float zg = sigmoidf_(iz + hz + bhh[j + HD]);
        const float ng = tanhf(inn + rg * (hn + bhh[j + 2 * HD]));
        const float hv = Hs[j * 33 + lane];
        const float val = (1.f - zg) * ng + zg * hv;
        Hnew_t[(size_t)j * BSZ + b] = val;
        if (Sum_t) Sum_t[(size_t)j * BSZ + b] = val + Xs[j * 33 + lane];
    }
}

// ---------------- GEMV: warp = 2 j (uniform weights), lanes = 32 b ------------------
__device__ void gemv_t(const float* __restrict__ Xs, int K4,
                       const float* __restrict__ W, const float* __restrict__ bias,
                       float* __restrict__ Y_t, int njp, int maxw)
{
    const int w = threadIdx.x >> 5, lane = threadIdx.x & 31;
    const int jp = (blockIdx.x >> 2) + (w << 5);
    if (w < maxw && jp < njp) {
        const int j0 = 2 * jp;
        const int b = ((blockIdx.x & 3) << 5) + lane;
        const float4* Wa = (const float4*)W + (size_t)j0 * K4;
        const float4* Wb = Wa + K4;
        float a0 = 0.f, a1 = 0.f;
#pragma unroll 8
        for (int k4 = 0; k4 < K4; k4++) {
            const float4 wa = Wa[k4], wb = Wb[k4];
            const float x0 = Xs[(4 * k4 + 0) * 33 + lane];
            const float x1 = Xs[(4 * k4 + 1) * 33 + lane];
            const float x2 = Xs[(4 * k4 + 2) * 33 + lane];
            const float x3 = Xs[(4 * k4 + 3) * 33 + lane];
            a0 = fmaf(wa.x, x0, a0); a0 = fmaf(wa.y, x1, a0);
            a0 = fmaf(wa.z, x2, a0); a0 = fmaf(wa.w, x3, a0);
            a1 = fmaf(wb.x, x0, a1); a1 = fmaf(wb.y, x1, a1);
            a1 = fmaf(wb.z, x2, a1); a1 = fmaf(wb.w, x3, a1);
        }
        Y_t[(size_t)j0 * BSZ + b]       = a0 + bias[j0];
        Y_t[(size_t)(j0 + 1) * BSZ + b] = a1 + bias[j0 + 1];
    }
}

// G: out rows (row-major final output)
__device__ void gemv_out(const float* __restrict__ Xs,
                         const float* __restrict__ W, const float* __restrict__ bias,
                         float* __restrict__ outp)
{
    const int w = threadIdx.x >> 5, lane = threadIdx.x & 31;
    const int jp = (blockIdx.x >> 2) + (w << 5);
    if (w < 8 && jp < 200) {
        const int j0 = 2 * jp;
        const int b = ((blockIdx.x & 3) << 5) + lane;
        const float4* Wa = (const float4*)W + (size_t)j0 * 64;
        const float4* Wb = Wa + 64;
        float a0 = 0.f, a1 = 0.f;
#pragma unroll 8
        for (int k4 = 0; k4 < 64; k4++) {
            const float4 wa = Wa[k4], wb = Wb[k4];
            const float x0 = Xs[(4 * k4 + 0) * 33 + lane];
            const float x1 = Xs[(4 * k4 + 1) * 33 + lane];
            const float x2 = Xs[(4 * k4 + 2) * 33 + lane];
            const float x3 = Xs[(4 * k4 + 3) * 33 + lane];
            a0 = fmaf(wa.x, x0, a0); a0 = fmaf(wa.y, x1, a0);
            a0 = fmaf(wa.z, x2, a0); a0 = fmaf(wa.w, x3, a0);
            a1 = fmaf(wb.x, x0, a1); a1 = fmaf(wb.y, x1, a1);
            a1 = fmaf(wb.z, x2, a1); a1 = fmaf(wb.w, x3, a1);
        }
        outp[(size_t)b * 80000 + j0]     = a0 + bias[j0];
        outp[(size_t)b * 80000 + j0 + 1] = a1 + bias[j0 + 1];
    }
}

// ---------------- fused attention (block = batch b) ---------------------------------
__device__ void dev_attn(const float* __restrict__ vw, const float* __restrict__ vb,
                         float* smf)
{
    float* qs   = smf;            // 256
    float* vs   = smf + 256;      // 256
    float* sexp = smf + 512;      // 512
    float* red  = smf + 1024;     // 16
    float* pacc = smf + 1040;     // 1024
    const int tid = threadIdx.x, lane = tid & 31, wid = tid >> 5;
    const int b = blockIdx.x;
    const float vb0 = vb[0];

    if (tid < HD) { qs[tid] = g_q[(size_t)tid * BSZ + b]; vs[tid] = vw[tid]; }
    __syncthreads();

    float2 q2[4], v2[4];
#pragma unroll
    for (int m = 0; m < 4; m++) {
        q2[m] = *(const float2*)(qs + 2 * (lane + m * 32));
        v2[m] = *(const float2*)(vs + 2 * (lane + m * 32));
    }
    const __half2* wb = (const __half2*)g_w1h + (size_t)b * TE * (HD / 2);
#pragma unroll 2
    for (int i = 0; i < 32; i++) {
        const int t = wid * 32 + i;
        const __half2* r2 = wb + (size_t)t * (HD / 2) + lane;
        float acc = 0.f;
#pragma unroll
        for (int m = 0; m < 4; m++) {
            float2 ww = __half22float2(r2[m * 32]);
            acc += v2[m].x * tanh_fast(ww.x + q2[m].x)
                 + v2[m].y * tanh_fast(ww.y + q2[m].y);
        }
        for (int o = 16; o; o >>= 1) acc += __shfl_down_sync(0xffffffffu, acc, o);
        if (lane == 0) sexp[t] = acc + vb0;
    }
    __syncthreads();

    float s = sexp[tid];
    float m_ = s;
    for (int o = 16; o; o >>= 1) m_ = fmaxf(m_, __shfl_xor_sync(0xffffffffu, m_, o));
    if (lane == 0) red[wid] = m_;
    __syncthreads();
    float mx = red[0];
#pragma unroll
    for (int k = 1; k < 16; k++) mx = fmaxf(mx, red[k]);
    float e = __expf(s - mx);
    float ss = e;
    for (int o = 16; o; o >>= 1) ss += __shfl_xor_sync(0xffffffffu, ss, o);
    __syncthreads();
    sexp[tid] = e;
    if (lane == 0) red[wid] = ss;
    __syncthreads();
    float sum = red[0];
#pragma unroll
    for (int k = 1; k < 16; k++) sum += red[k];
    const float inv = 1.f / sum;

    const int h2 = tid & 127, tq = tid >> 7;
    const __half2* e2 = (const __half2*)g_ench
                      + ((size_t)b * TE + tq * 128) * (HD / 2) + h2;
    float ax = 0.f, ay = 0.f;
#pragma unroll 8
    for (int tt = 0; tt < 128; tt++) {
        float2 v = __half22float2(e2[(size_t)tt * (HD / 2)]);
        float uu = sexp[tq * 128 + tt];
        ax = fmaf(uu, v.x, ax); ay = fmaf(uu, v.y, ay);
    }
    pacc[tq * 256 + h2 * 2]     = ax;
    pacc[tq * 256 + h2 * 2 + 1] = ay;
    __syncthreads();
    if (tid < HD) {
        float r = pacc[tid] + pacc[256 + tid] + pacc[512 + tid] + pacc[768 + tid];
        g_ddot[(size_t)tid * BSZ + b] = r * inv;
    }
}

// ---------------- prelude tiled GEMM (32 rows x 64 cols per tile) -------------------
// tmode=1: store transposed-per-step: Y[(r>>7)*G3*128 + j*128 + (r&127)]
__device__ void dev_linear(const float* __restrict__ X, const float* __restrict__ dec,
                           int nf4, const float* __restrict__ W,
                           const float* __restrict__ bias,
                           float* __restrict__ Yf, __half* __restrict__ Yh,
                           int ldy, int relu, int nrt, int ncp, float4* sm4, int tmode)
{
    const int tid = threadIdx.x, lane = tid & 31, wid = tid >> 5;
    const int stride4 = nf4 + 1;
    const int tiles = nrt * ncp;
    for (int t = blockIdx.x; t < tiles; t += GRID) {
        const int rt = t / ncp, cp = t - rt * ncp;
        const long r0 = (long)rt * 32;
        for (int idx = tid; idx < 32 * nf4; idx += NTHR) {
            int row = idx / nf4, c4 = idx - row * nf4;
            long r = r0 + row;
            float4 v;
            if (dec) v = *(const float4*)(dec + (r & 127) * 80000L
                                          + (r >> 7) * (RF * MELD) + c4 * 4);
            else     v = *(const float4*)(X + r * (long)(nf4 * 4) + c4 * 4);
            sm4[row * stride4 + c4] = v;
        }
        __syncthreads();
        const int j0 = cp * 64 + wid * 4;
        const float4* W4 = (const float4*)W + (size_t)j0 * nf4;
        const float4* xr = sm4 + lane * stride4;
        float a0 = bias[j0], a1 = bias[j0 + 1], a2 = bias[j0 + 2], a3 = bias[j0 + 3];
#pragma unroll 4
        for (int k = 0; k < nf4; k++) {
            float4 x = xr[k];
            float4 w0 = W4[k];
            a0 = fmaf(w0.x, x.x, a0); a0 = fmaf(w0.y, x.y, a0);
            a0 = fmaf(w0.z, x.z, a0); a0 = fmaf(w0.w, x.w, a0);
            float4 w1 = W4[nf4 + k];
            a1 = fmaf(w1.x, x.x, a1); a1 = fmaf(w1.y, x.y, a1);
            a1 = fmaf(w1.z, x.z, a1); a1 = fmaf(w1.w, x.w, a1);
            float4 w2 = W4[2 * nf4 + k];
            a2 = fmaf(w2.x, x.x, a2); a2 = fmaf(w2.y, x.y, a2);
            a2 = fmaf(w2.z, x.z, a2); a2 = fmaf(w2.w, x.w, a2);
            float4 w3 = W4[3 * nf4 + k];
            a3 = fmaf(w3.x, x.x, a3); a3 = fmaf(w3.y, x.y, a3);
            a3 = fmaf(w3.z, x.z, a3); a3 = fmaf(w3.w, x.w, a3);
        }
        if (relu) {
            a0 = fmaxf(a0, 0.f); a1 = fmaxf(a1, 0.f);
            a2 = fmaxf(a2, 0.f); a3 = fmaxf(a3, 0.f);
        }
        const long r = r0 + lane;
        if (tmode) {
            const size_t baseo = (size_t)(r >> 7) * (G3 * BSZ) + (r & 127);
            Yf[baseo + (size_t)(j0 + 0) * BSZ] = a0;
            Yf[baseo + (size_t)(j0 + 1) * BSZ] = a1;
            Yf[baseo + (size_t)(j0 + 2) * BSZ] = a2;
            Yf[baseo + (size_t)(j0 + 3) * BSZ] = a3;
        } else if (Yh) {
            const long orow = r * (long)ldy + j0;
            Yh[orow] = __float2half(a0);     Yh[orow + 1] = __float2half(a1);
            Yh[orow + 2] = __float2half(a2); Yh[orow + 3] = __float2half(a3);
        } else {
            const long orow = r * (long)ldy + j0;
            Yf[orow] = a0; Yf[orow + 1] = a1; Yf[orow + 2] = a2; Yf[orow + 3] = a3;
        }
        __syncthreads();
    }
}

// ---------------- persistent kernel -------------------------------------------------
__global__ void __launch_bounds__(NTHR, 1)
mel_persist(const float* __restrict__ enc, const float* __restrict__ dec,
            const float* pre_w1, const float* pre_b1,
            const float* pre_w2, const float* pre_b2,
            const float* w1, const float* b1, const float* w2, const float* b2,
            const float* v_w, const float* v_b,
            const float* proj_w, const float* proj_b,
            const float* out_w, const float* out_b,
            const float* att_wih, const float* att_whh,
            const float* att_bih, const float* att_bhh,
            const float* g1_wih, const float* g1_whh,
            const float* g1_bih, const float* g1_bhh,
            const float* g2_wih, const float* g2_whh,
            const float* g2_bih, const float* g2_bhh,
            float* __restrict__ out)
{
    extern __shared__ float4 sm4[];
    float* xs = (float*)sm4;            // [256][33]
    float* hs = xs + XS_F;              // [256][33]
    float* smattn = xs + ATTN_F;        // 2064 floats
    const unsigned base = ld_acq(&g_bar_epoch);
    unsigned ep = 0;
#define GS() gsync(base + (++ep))

    // P0: zero states + fp16 copy of enc
    {
        const int gtid = blockIdx.x * NTHR + threadIdx.x;
        for (int i = gtid; i < HD * BSZ; i += GRID * NTHR) {
            g_dbuf[0][i] = 0.f;  g_dbuf[1][i] = 0.f;
            g_h1buf[0][i] = 0.f; g_h1buf[1][i] = 0.f;
            g_h2buf[0][i] = 0.f; g_h2buf[1][i] = 0.f;
        }
        const float4* e4 = (const float4*)enc;
        __half2* o2 = (__half2*)g_ench;
        const int n4 = (BSZ * TE * HD) / 4;
        for (int i = gtid; i < n4; i += GRID * NTHR) {
            float4 v = e4[i];
            o2[2 * i]     = __floats2half2_rn(v.x, v.y);
            o2[2 * i + 1] = __floats2half2_rn(v.z, v.w);
        }
    }
    // P1..P4 prelude GEMMs
    dev_linear(nullptr, dec, 20, pre_w1, pre_b1, g_pre1, nullptr, HD, 1, 800, 4, sm4, 0);
    GS();
    dev_linear(g_pre1, nullptr, 64, pre_w2, pre_b2, g_xs, nullptr, 128, 1, 800, 2, sm4, 0);
    GS();
    dev_linear(g_xs, nullptr, 32, att_wih, att_bih, g_giatt, nullptr, 0, 0, 800, 12, sm4, 1);
    GS();
    dev_linear(enc, nullptr, 64, w1, b1, nullptr, g_w1h, HD, 0, 2048, 4, sm4, 0);
    GS();

    for (int i = 0; i < STEPS; i++) {
        const int cur = i & 1, prev = cur ^ 1;

        // A: attention GRU
        stage_t(g_dbuf[prev], 256, xs);
        __syncthreads();
        gru_t(g_giatt + (size_t)i * G3 * BSZ, nullptr, nullptr,
              att_whh, att_bhh, xs, nullptr, g_dbuf[cur], nullptr);
        GS();
        // B: q = d @ w2^T + b2
        stage_t(g_dbuf[cur], 256, xs);
        __syncthreads();
        gemv_t(xs, 64, w2, b2, g_q, 128, 4);
        GS();
        // C: attention (uses its own smem region; xs keeps dcur staged)
        dev_attn(v_w, v_b, smattn);
        GS();
        // D: p = [d | ddot] @ proj^T  (dcur still in xs; ddot staged into hs = xs+256 rows)
        stage_t(g_ddot, 256, hs);
        __syncthreads();
        gemv_t(xs, 128, proj_w, proj_b, g_p, 128, 4);
        GS();
        // E: GRU1; in2 = p + o1
        stage_t(g_p, 256, xs);
        stage_t(g_h1buf[prev], 256, hs);
        __syncthreads();
        gru_t(nullptr, g1_wih, g1_bih, g1_whh, g1_bhh, hs, xs,
              g_h1buf[cur], g_in2);
        GS();
        // F: GRU2; s = in2 + o2
        stage_t(g_in2, 256, xs);
        stage_t(g_h2buf[prev], 256, hs);
        __syncthreads();
        gru_t(nullptr, g2_wih, g2_bih, g2_whh, g2_bhh, hs, xs,
              g_h2buf[cur], g_s);
        GS();
        // G: out rows (no grid barrier; next-A's write target is disjoint)
        stage_t(g_s, 256, xs);
        __syncthreads();
        gemv_out(xs, out_w, out_b, out + (size_t)i * RF * MELD);
        __syncthreads();   // block-local: xs reused by next-A staging
    }
#undef GS
}

// ---------------- host launch -------------------------------------------------------
extern "C" void kernel_launch(void* const* d_in, const int* in_sizes, int n_in,
                              void* d_out, int out_size)
{
    cudaFuncSetAttribute(mel_persist, cudaFuncAttributeMaxDynamicSharedMemorySize,
                         SMEM_BYTES);
    mel_persist<<<GRID, NTHR, SMEM_BYTES>>>(
        (const float*)d_in[0],  (const float*)d_in[1],
        (const float*)d_in[2],  (const float*)d_in[3],
        (const float*)d_in[4],  (const float*)d_in[5],
        (const float*)d_in[6],  (const float*)d_in[7],
        (const float*)d_in[8],  (const float*)d_in[9],
        (const float*)d_in[10], (const float*)d_in[11],
        (const float*)d_in[12], (const float*)d_in[13],
        (const float*)d_in[14], (const float*)d_in[15],
        (const float*)d_in[16], (const float*)d_in[17],
        (const float*)d_in[18], (const float*)d_in[19],
        (const float*)d_in[20], (const float*)d_in[21],
        (const float*)d_in[22], (const float*)d_in[23],
        (const float*)d_in[24], (const float*)d_in[25],
        (const float*)d_in[26], (const float*)d_in[27],
        (float*)d_out);
}

// round 12
// speedup vs baseline: 2.7330x; 1.0071x over previous
#include <cuda_runtime.h>
#include <cuda_fp16.h>
#include <cstdint>

#define GRID  128
#define NTHR  512
#define BSZ   128
#define TE    512
#define HD    256
#define MELD  80
#define RF    5
#define STEPS 200
#define G3    768
// smem: xs[256*32] + hs[256*32] floats + scratch region 2064 floats
#define XS_F   (256 * 32)
#define SCR_F  (2 * XS_F)
#define SMEM_BYTES ((SCR_F + 2064) * 4)   // 73,792 B

// ---------------- device scratch (step vectors transposed [dim][BSZ]) ----------------
__device__ __half g_w1h[(size_t)BSZ * TE * HD];
__device__ __half g_ench[(size_t)BSZ * TE * HD];
__device__ float g_pre1[STEPS * BSZ * HD];
__device__ float g_xs[STEPS * BSZ * (HD / 2)];
__device__ float g_giatt[(size_t)STEPS * G3 * BSZ];  // [step][j][b]
__device__ float g_dbuf[2][HD * BSZ];
__device__ float g_h1buf[2][HD * BSZ];
__device__ float g_h2buf[2][HD * BSZ];
__device__ float g_q[HD * BSZ];
__device__ float g_ddot[HD * BSZ];
__device__ float g_p[HD * BSZ];
__device__ float g_in2[HD * BSZ];
__device__ float g_s[HD * BSZ];
__device__ unsigned g_bar_leaf[8];
__device__ unsigned g_bar_root;
__device__ unsigned g_bar_epoch;

// ---------------- helpers ------------------------------------------------------------
__device__ __forceinline__ float tanh_fast(float x) {
    float y; asm("tanh.approx.f32 %0, %1;" : "=f"(y) : "f"(x)); return y;
}
__device__ __forceinline__ float sigmoidf_(float x) { return 1.f / (1.f + __expf(-x)); }
__device__ __forceinline__ unsigned ld_acq(const unsigned* p) {
    unsigned v; asm volatile("ld.acquire.gpu.b32 %0, [%1];" : "=r"(v) : "l"(p)); return v;
}

// Tree barrier: 8 leaves x 16 blocks, then 8-way root.
__device__ __forceinline__ void gsync(unsigned target)
{
    __syncthreads();
    if (threadIdx.x == 0) {
        __threadfence();
        const int lf = blockIdx.x & 7;
        if (atomicAdd(&g_bar_leaf[lf], 1u) == 15u) {
            g_bar_leaf[lf] = 0u;           // members of this leaf are epoch-spinning
            __threadfence();
            if (atomicAdd(&g_bar_root, 1u) == 7u) {
                g_bar_root = 0u;
                __threadfence();
                atomicAdd(&g_bar_epoch, 1u);
            } else {
                while ((int)(ld_acq(&g_bar_epoch) - target) < 0) { }
            }
        } else {
            while ((int)(ld_acq(&g_bar_epoch) - target) < 0) { }
        }
    }
    __syncthreads();
}

// ---------------- staging: src_t [K][128] -> smem [K][32] (this block's b-tile) ------
__device__ __forceinline__ void stage_t(const float* __restrict__ src, int K,
                                        float* __restrict__ xs)
{
    const int b0 = (blockIdx.x & 3) << 5;
    const int n = K * 8;                     // 8 float4 per row of 32
    for (int idx = threadIdx.x; idx < n; idx += NTHR) {
        const int k = idx >> 3, q = idx & 7;
        *(float4*)(xs + k * 32 + 4 * q) = *(const float4*)(src + (size_t)k * BSZ + b0 + 4 * q);
    }
}

// ---------------- GRU: 16 warps = 8 j-slots x 2 K-halves -----------------------------
__device__ void gru_t(const float* __restrict__ gi_t,
                      const float* __restrict__ Wih, const float* __restrict__ bih,
                      const float* __restrict__ Whh, const float* __restrict__ bhh,
                      const float* __restrict__ Hs, const float* __restrict__ Xs,
                      float* __restrict__ Hnew_t, float* __restrict__ Sum_t,
                      float* __restrict__ part)
{
    const int w = threadIdx.x >> 5, lane = threadIdx.x & 31;
    const int wl = w & 7, up = w >> 3;
    const int j = (blockIdx.x >> 2) + (wl << 5);
    const int b = ((blockIdx.x & 3) << 5) + lane;
    const int k0 = up << 5;                        // float4 offset: 0 or 32

    const float4* Wr4 = (const float4*)Whh + (size_t)j * 64 + k0;
    const float4* Wz4 = Wr4 + (size_t)HD * 64;
    const float4* Wn4 = Wz4 + (size_t)HD * 64;
    float hr = 0.f, hz = 0.f, hn = 0.f;
#pragma unroll 8
    for (int k4 = 0; k4 < 32; k4++) {
        const int kk = (k0 + k4) << 2;
        const float4 a = Wr4[k4], c = Wz4[k4], d = Wn4[k4];
        const float h0 = Hs[(kk + 0) * 32 + lane];
        const float h1 = Hs[(kk + 1) * 32 + lane];
        const float h2 = Hs[(kk + 2) * 32 + lane];
        const float h3 = Hs[(kk + 3) * 32 + lane];
        hr = fmaf(a.x, h0, hr); hr = fmaf(a.y, h1, hr);
        hr = fmaf(a.z, h2, hr); hr = fmaf(a.w, h3, hr);
        hz = fmaf(c.x, h0, hz); hz = fmaf(c.y, h1, hz);
        hz = fmaf(c.z, h2, hz); hz = fmaf(c.w, h3, hz);
        hn = fmaf(d.x, h0, hn); hn = fmaf(d.y, h1, hn);
        hn = fmaf(d.z, h2, hn); hn = fmaf(d.w, h3, hn);
    }
    float xr = 0.f, xz = 0.f, xn = 0.f;
    if (Wih) {
        const float4* Ur4 = (const float4*)Wih + (size_t)j * 64 + k0;
        const float4* Uz4 = Ur4 + (size_t)HD * 64;
        const float4* Un4 = Uz4 + (size_t)HD * 64;
#pragma unroll 8
        for (int k4 = 0; k4 < 32; k4++) {
            const int kk = (k0 + k4) << 2;
            const float4 a = Ur4[k4], c = Uz4[k4], d = Un4[k4];
            const float x0 = Xs[(kk + 0) * 32 + lane];
            const float x1 = Xs[(kk + 1) * 32 + lane];
            const float x2 = Xs[(kk + 2) * 32 + lane];
            const float x3 = Xs[(kk + 3) * 32 + lane];
            xr = fmaf(a.x, x0, xr); xr = fmaf(a.y, x1, xr);
            xr = fmaf(a.z, x2, xr); xr = fmaf(a.w, x3, xr);
            xz = fmaf(c.x, x0, xz); xz = fmaf(c.y, x1, xz);
            xz = fmaf(c.z, x2, xz); xz = fmaf(c.w, x3, xz);
            xn = fmaf(d.x, x0, xn); xn = fmaf(d.y, x1, xn);
            xn = fmaf(d.z, x2, xn); xn = fmaf(d.w, x3, xn);
        }
    }
    if (up) {
        float* pp = part + (wl * 6) * 32 + lane;
        pp[0]       = hr; pp[32]      = hz; pp[64]      = hn;
        pp[96]      = xr; pp[128]     = xz; pp[160]     = xn;
    }
    __syncthreads();
    if (!up) {
        const float* pp = part + (wl * 6) * 32 + lane;
        hr += pp[0]; hz += pp[32]; hn += pp[64];
        float ir, iz, inn;
        if (gi_t) {
            ir  = gi_t[(size_t)j * BSZ + b];
            iz  = gi_t[(size_t)(j + HD) * BSZ + b];
            inn = gi_t[(size_t)(j + 2 * HD) * BSZ + b];
        } else {
            ir  = xr + pp[96]  + bih[j];
            iz  = xz + pp[128] + bih[j + HD];
            inn = xn + pp[160] + bih[j + 2 * HD];
        }
        const float rg = sigmoidf_(ir + hr + bhh[j]);
        const float zg = sigmoidf_(iz + hz + bhh[j + HD]);
        const float ng = tanhf(inn + rg * (hn + bhh[j + 2 * HD]));
        const float hv = Hs[j * 32 + lane];
        const float val = (1.f - zg) * ng + zg * hv;
        Hnew_t[(size_t)j * BSZ + b] = val;
        if (Sum_t) Sum_t[(size_t)j * BSZ + b] = val + Xs[j * 32 + lane];
    }
    __syncthreads();
}

// ---------------- GEMV (njp=128): 16 warps = 4 jp-groups x 4 K-splits ----------------
__device__ void gemv_t(const float* __restrict__ Xs, int K4,
                       const float* __restrict__ W, const float* __restrict__ bias,
                       float* __restrict__ Y_t, float* __restrict__ part)
{
    const int w = threadIdx.x >> 5, lane = threadIdx.x & 31;
    const int g = w & 3, ks = w >> 2;
    const int jp = (blockIdx.x >> 2) + (g << 5);
    const int j0 = 2 * jp;
    const int b = ((blockIdx.x & 3) << 5) + lane;
    const int kq = K4 >> 2;
    const float4* Wa = (const float4*)W + (size_t)j0 * K4 + ks * kq;
    const float4* Wb = Wa + K4;
    float a0 = 0.f, a1 = 0.f;
#pragma unroll 8
    for (int k4 = 0; k4 < kq; k4++) {
        const int kk = (ks * kq + k4) << 2;
        const float4 wa = Wa[k4], wb = Wb[k4];
        const float x0 = Xs[(kk + 0) * 32 + lane];
        const float x1 = Xs[(kk + 1) * 32 + lane];
        const float x2 = Xs[(kk + 2) * 32 + lane];
        const float x3 = Xs[(kk + 3) * 32 + lane];
        a0 = fmaf(wa.x, x0, a0); a0 = fmaf(wa.y, x1, a0);
        a0 = fmaf(wa.z, x2, a0); a0 = fmaf(wa.w, x3, a0);
        a1 = fmaf(wb.x, x0, a1); a1 = fmaf(wb.y, x1, a1);
        a1 = fmaf(wb.z, x2, a1); a1 = fmaf(wb.w, x3, a1);
    }
    if (ks) {
        float* pp = part + ((ks - 1) * 4 + g) * 64 + lane;
        pp[0] = a0; pp[32] = a1;
    }
    __syncthreads();
    if (!ks) {
        const float* pp = part + g * 64 + lane;
        a0 += pp[0]   + pp[256]  + pp[512];
        a1 += pp[32]  + pp[288]  + pp[544];
        Y_t[(size_t)j0 * BSZ + b]       = a0 + bias[j0];
        Y_t[(size_t)(j0 + 1) * BSZ + b] = a1 + bias[j0 + 1];
    }
    __syncthreads();
}

// ---------------- G: out rows, 16 warps = 8 jp-groups x 2 K-splits -------------------
__device__ void gemv_out(const float* __restrict__ Xs,
                         const float* __restrict__ W, const float* __restrict__ bias,
                         float* __restrict__ outp, float* __restrict__ part)
{
    const int w = threadIdx.x >> 5, lane = threadIdx.x & 31;
    const int g = w & 7, ks = w >> 3;
    const int jp = (blockIdx.x >> 2) + (g << 5);
    const bool valid = jp < 200;
    const int j0 = 2 * jp;
    const int b = ((blockIdx.x & 3) << 5) + lane;
    float a0 = 0.f, a1 = 0.f;
    if (valid) {
        const float4* Wa = (const float4*)W + (size_t)j0 * 64 + ks * 32;
        const float4* Wb = Wa + 64;
#pragma unroll 8
        for (int k4 = 0; k4 < 32; k4++) {
            const int kk = (ks * 32 + k4) << 2;
            const float4 wa = Wa[k4], wb = Wb[k4];
            const float x0 = Xs[(kk + 0) * 32 + lane];
            const float x1 = Xs[(kk + 1) * 32 + lane];
            const float x2 = Xs[(kk + 2) * 32 + lane];
            const float x3 = Xs[(kk + 3) * 32 + lane];
            a0 = fmaf(wa.x, x0, a0); a0 = fmaf(wa.y, x1, a0);
            a0 = fmaf(wa.z, x2, a0); a0 = fmaf(wa.w, x3, a0);
            a1 = fmaf(wb.x, x0, a1); a1 = fmaf(wb.y, x1, a1);
            a1 = fmaf(wb.z, x2, a1); a1 = fmaf(wb.w, x3, a1);
        }
        if (ks) { float* pp = part + g * 64 + lane; pp[0] = a0; pp[32] = a1; }
    }
    __syncthreads();
    if (valid && !ks) {
        const float* pp = part + g * 64 + lane;
        a0 += pp[0]; a1 += pp[32];
        outp[(size_t)b * 80000 + j0]     = a0 + bias[j0];
        outp[(size_t)b * 80000 + j0 + 1] = a1 + bias[j0 + 1];
    }
    __syncthreads();
}

// ---------------- fused attention (block = batch b) ----------------------------------
__device__ void dev_attn(const float* __restrict__ vw, const float* __restrict__ vb,
                         float* smf)
{
    float* qs   = smf;            // 256
    float* vs   = smf + 256;      // 256
    float* sexp = smf + 512;      // 512
    float* red  = smf + 1024;     // 16
    float* pacc = smf + 1040;     // 1024
    const int tid = threadIdx.x, lane = tid & 31, wid = tid >> 5;
    const int b = blockIdx.x;
    const float vb0 = vb[0];

    if (tid < HD) { qs[tid] = g_q[(size_t)tid * BSZ + b]; vs[tid] = vw[tid]; }
    __syncthreads();

    float2 q2[4], v2[4];
#pragma unroll
    for (int m = 0; m < 4; m++) {
        q2[m] = *(const float2*)(qs + 2 * (lane + m * 32));
        v2[m] = *(const float2*)(vs + 2 * (lane + m * 32));
    }
    const __half2* wb = (const __half2*)g_w1h + (size_t)b * TE * (HD / 2);
#pragma unroll 2
    for (int i = 0; i < 32; i++) {
        const int t = wid * 32 + i;
        const __half2* r2 = wb + (size_t)t * (HD / 2) + lane;
        float acc = 0.f;
#pragma unroll
        for (int m = 0; m < 4; m++) {
            float2 ww = __half22float2(r2[m * 32]);
            acc += v2[m].x * tanh_fast(ww.x + q2[m].x)
                 + v2[m].y * tanh_fast(ww.y + q2[m].y);
        }
        for (int o = 16; o; o >>= 1) acc += __shfl_down_sync(0xffffffffu, acc, o);
        if (lane == 0) sexp[t] = acc + vb0;
    }
    __syncthreads();

    float s = sexp[tid];
    float m_ = s;
    for (int o = 16; o; o >>= 1) m_ = fmaxf(m_, __shfl_xor_sync(0xffffffffu, m_, o));
    if (lane == 0) red[wid] = m_;
    __syncthreads();
    float mx = red[0];
#pragma unroll
    for (int k = 1; k < 16; k++) mx = fmaxf(mx, red[k]);
    float e = __expf(s - mx);
    float ss = e;
    for (int o = 16; o; o >>= 1) ss += __shfl_xor_sync(0xffffffffu, ss, o);
    __syncthreads();
    sexp[tid] = e;
    if (lane == 0) red[wid] = ss;
    __syncthreads();
    float sum = red[0];
#pragma unroll
    for (int k = 1; k < 16; k++) sum += red[k];
    const float inv = 1.f / sum;

    const int h2 = tid & 127, tq = tid >> 7;
    const __half2* e2 = (const __half2*)g_ench
                      + ((size_t)b * TE + tq * 128) * (HD / 2) + h2;
    float ax = 0.f, ay = 0.f;
#pragma unroll 8
    for (int tt = 0; tt < 128; tt++) {
        float2 v = __half22float2(e2[(size_t)tt * (HD / 2)]);
        float uu = sexp[tq * 128 + tt];
        ax = fmaf(uu, v.x, ax); ay = fmaf(uu, v.y, ay);
    }
    pacc[tq * 256 + h2 * 2]     = ax;
    pacc[tq * 256 + h2 * 2 + 1] = ay;
    __syncthreads();
    if (tid < HD) {
        float r = pacc[tid] + pacc[256 + tid] + pacc[512 + tid] + pacc[768 + tid];
        g_ddot[(size_t)tid * BSZ + b] = r * inv;
    }
    __syncthreads();
}

// ---------------- prelude tiled GEMM (unchanged from R10) ----------------------------
__device__ void dev_linear(const float* __restrict__ X, const float* __restrict__ dec,
                           int nf4, const float* __restrict__ W,
                           const float* __restrict__ bias,
                           float* __restrict__ Yf, __half* __restrict__ Yh,
                           int ldy, int relu, int nrt, int ncp, float4* sm4, int tmode)
{
    const int tid = threadIdx.x, lane = tid & 31, wid = tid >> 5;
    const int stride4 = nf4 + 1;
    const int tiles = nrt * ncp;
    for (int t = blockIdx.x; t < tiles; t += GRID) {
        const int rt = t / ncp, cp = t - rt * ncp;
        const long r0 = (long)rt * 32;
        for (int idx = tid; idx < 32 * nf4; idx += NTHR) {
            int row = idx / nf4, c4 = idx - row * nf4;
            long r = r0 + row;
            float4 v;
            if (dec) v = *(const float4*)(dec + (r & 127) * 80000L
                                          + (r >> 7) * (RF * MELD) + c4 * 4);
            else     v = *(const float4*)(X + r * (long)(nf4 * 4) + c4 * 4);
            sm4[row * stride4 + c4] = v;
        }
        __syncthreads();
        const int j0 = cp * 64 + wid * 4;
        const float4* W4 = (const float4*)W + (size_t)j0 * nf4;
        const float4* xr = sm4 + lane * stride4;
        float a0 = bias[j0], a1 = bias[j0 + 1], a2 = bias[j0 + 2], a3 = bias[j0 + 3];
#pragma unroll 4
        for (int k = 0; k < nf4; k++) {
            float4 x = xr[k];
            float4 w0 = W4[k];
            a0 = fmaf(w0.x, x.x, a0); a0 = fmaf(w0.y, x.y, a0);
            a0 = fmaf(w0.z, x.z, a0); a0 = fmaf(w0.w, x.w, a0);
            float4 w1 = W4[nf4 + k];
            a1 = fmaf(w1.x, x.x, a1); a1 = fmaf(w1.y, x.y, a1);
            a1 = fmaf(w1.z, x.z, a1); a1 = fmaf(w1.w, x.w, a1);
            float4 w2 = W4[2 * nf4 + k];
            a2 = fmaf(w2.x, x.x, a2); a2 = fmaf(w2.y, x.y, a2);
            a2 = fmaf(w2.z, x.z, a2); a2 = fmaf(w2.w, x.w, a2);
            float4 w3 = W4[3 * nf4 + k];
            a3 = fmaf(w3.x, x.x, a3); a3 = fmaf(w3.y, x.y, a3);
            a3 = fmaf(w3.z, x.z, a3); a3 = fmaf(w3.w, x.w, a3);
        }
        if (relu) {
            a0 = fmaxf(a0, 0.f); a1 = fmaxf(a1, 0.f);
            a2 = fmaxf(a2, 0.f); a3 = fmaxf(a3, 0.f);
        }
        const long r = r0 + lane;
        if (tmode) {
            const size_t baseo = (size_t)(r >> 7) * (G3 * BSZ) + (r & 127);
            Yf[baseo + (size_t)(j0 + 0) * BSZ] = a0;
            Yf[baseo + (size_t)(j0 + 1) * BSZ] = a1;
            Yf[baseo + (size_t)(j0 + 2) * BSZ] = a2;
            Yf[baseo + (size_t)(j0 + 3) * BSZ] = a3;
        } else if (Yh) {
            const long orow = r * (long)ldy + j0;
            Yh[orow] = __float2half(a0);     Yh[orow + 1] = __float2half(a1);
            Yh[orow + 2] = __float2half(a2); Yh[orow + 3] = __float2half(a3);
        } else {
            const long orow = r * (long)ldy + j0;
            Yf[orow] = a0; Yf[orow + 1] = a1; Yf[orow + 2] = a2; Yf[orow + 3] = a3;
        }
        __syncthreads();
    }
}

// ---------------- persistent kernel --------------------------------------------------
__global__ void __launch_bounds__(NTHR, 1)
mel_persist(const float* __restrict__ enc, const float* __restrict__ dec,
            const float* pre_w1, const float* pre_b1,
            const float* pre_w2, const float* pre_b2,
            const float* w1, const float* b1, const float* w2, const float* b2,
            const float* v_w, const float* v_b,
            const float* proj_w, const float* proj_b,
            const float* out_w, const float* out_b,
            const float* att_wih, const float* att_whh,
            const float* att_bih, const float* att_bhh,
            const float* g1_wih, const float* g1_whh,
            const float* g1_bih, const float* g1_bhh,
            const float* g2_wih, const float* g2_whh,
            const float* g2_bih, const float* g2_bhh,
            float* __restrict__ out)
{
    extern __shared__ float4 sm4[];
    float* xs  = (float*)sm4;           // [256][32]
    float* hs  = xs + XS_F;             // [256][32]
    float* scr = xs + SCR_F;            // 2064 floats: attn smem / K-split partials
    const unsigned base = ld_acq(&g_bar_epoch);
    unsigned ep = 0;
#define GS() gsync(base + (++ep))

    // P0: zero states + fp16 copy of enc
    {
        const int gtid = blockIdx.x * NTHR + threadIdx.x;
        for (int i = gtid; i < HD * BSZ; i += GRID * NTHR) {
            g_dbuf[0][i] = 0.f;  g_dbuf[1][i] = 0.f;
            g_h1buf[0][i] = 0.f; g_h1buf[1][i] = 0.f;
            g_h2buf[0][i] = 0.f; g_h2buf[1][i] = 0.f;
        }
        const float4* e4 = (const float4*)enc;
        __half2* o2 = (__half2*)g_ench;
        const int n4 = (BSZ * TE * HD) / 4;
        for (int i = gtid; i < n4; i += GRID * NTHR) {
            float4 v = e4[i];
            o2[2 * i]     = __floats2half2_rn(v.x, v.y);
            o2[2 * i + 1] = __floats2half2_rn(v.z, v.w);
        }
    }
    // P1..P4 prelude GEMMs
    dev_linear(nullptr, dec, 20, pre_w1, pre_b1, g_pre1, nullptr, HD, 1, 800, 4, sm4, 0);
    GS();
    dev_linear(g_pre1, nullptr, 64, pre_w2, pre_b2, g_xs, nullptr, 128, 1, 800, 2, sm4, 0);
    GS();
    dev_linear(g_xs, nullptr, 32, att_wih, att_bih, g_giatt, nullptr, 0, 0, 800, 12, sm4, 1);
    GS();
    dev_linear(enc, nullptr, 64, w1, b1, nullptr, g_w1h, HD, 0, 2048, 4, sm4, 0);
    GS();

    for (int i = 0; i < STEPS; i++) {
        const int cur = i & 1, prev = cur ^ 1;

        // A: attention GRU (input gates precomputed)
        stage_t(g_dbuf[prev], 256, xs);
        __syncthreads();
        gru_t(g_giatt + (size_t)i * G3 * BSZ, nullptr, nullptr,
              att_whh, att_bhh, xs, nullptr, g_dbuf[cur], nullptr, scr);
        GS();
        // B: q = d @ w2^T + b2
        stage_t(g_dbuf[cur], 256, xs);
        __syncthreads();
        gemv_t(xs, 64, w2, b2, g_q, scr);
        GS();
        // C: attention
        dev_attn(v_w, v_b, scr);
        GS();
        // D: p = [d | ddot] @ proj^T (d still staged in xs; ddot staged into hs)
        stage_t(g_ddot, 256, hs);
        __syncthreads();
        gemv_t(xs, 128, proj_w, proj_b, g_p, scr);
        GS();
        // E: GRU1; in2 = p + o1
        stage_t(g_p, 256, xs);
        stage_t(g_h1buf[prev], 256, hs);
        __syncthreads();
        gru_t(nullptr, g1_wih, g1_bih, g1_whh, g1_bhh, hs, xs,
              g_h1buf[cur], g_in2, scr);
        GS();
        // F: GRU2; s = in2 + o2
        stage_t(g_in2, 256, xs);
        stage_t(g_h2buf[prev], 256, hs);
        __syncthreads();
        gru_t(nullptr, g2_wih, g2_bih, g2_whh, g2_bhh, hs, xs,
              g_h2buf[cur], g_s, scr);
        GS();
        // G: out rows (no grid barrier; next-A write target is disjoint)
        stage_t(g_s, 256, xs);
        __syncthreads();
        gemv_out(xs, out_w, out_b, out + (size_t)i * RF * MELD, scr);
    }
#undef GS
}

// ---------------- host launch --------------------------------------------------------
extern "C" void kernel_launch(void* const* d_in, const int* in_sizes, int n_in,
                              void* d_out, int out_size)
{
    cudaFuncSetAttribute(mel_persist, cudaFuncAttributeMaxDynamicSharedMemorySize,
                         SMEM_BYTES);
    mel_persist<<<GRID, NTHR, SMEM_BYTES>>>(
        (const float*)d_in[0],  (const float*)d_in[1],
        (const float*)d_in[2],  (const float*)d_in[3],
        (const float*)d_in[4],  (const float*)d_in[5],
        (const float*)d_in[6],  (const float*)d_in[7],
        (const float*)d_in[8],  (const float*)d_in[9],
        (const float*)d_in[10], (const float*)d_in[11],
        (const float*)d_in[12], (const float*)d_in[13],
        (const float*)d_in[14], (const float*)d_in[15],
        (const float*)d_in[16], (const float*)d_in[17],
        (const float*)d_in[18], (const float*)d_in[19],
        (const float*)d_in[20], (const float*)d_in[21],
        (const float*)d_in[22], (const float*)d_in[23],
        (const float*)d_in[24], (const float*)d_in[25],
        (const float*)d_in[26], (const float*)d_in[27],
        (float*)d_out);
}